// round 1
// baseline (speedup 1.0000x reference)
#include <cuda_runtime.h>
#include <cuda_fp16.h>
#include <mma.h>
#include <cstdint>

using namespace nvcuda;

// Problem constants
#define BB   2
#define SSEQ 1024
#define DD   768
#define HH   12
#define DKK  768
#define DVV  768
#define DHH  64          // DV / H
#define MROWS (BB*SSEQ)  // 2048
#define NBH   (BB*HH)    // 24

// ---------------- scratch (device globals; no allocation allowed) ----------------
__device__ float g_q_r[MROWS*DKK];
__device__ float g_q_i[MROWS*DKK];
__device__ float g_k_r[MROWS*DKK];
__device__ float g_k_i[MROWS*DKK];
__device__ float g_v_r[MROWS*DVV];
__device__ float g_v_i[MROWS*DVV];
__device__ float g_cb_r[NBH*SSEQ];
__device__ float g_cb_i[NBH*SSEQ];
__device__ float g_s_r[(size_t)NBH*SSEQ*SSEQ];   // ~100 MB
__device__ float g_s_i[(size_t)NBH*SSEQ*SSEQ];   // ~100 MB
__device__ __half g_p_r[(size_t)NBH*SSEQ*SSEQ];  // ~50 MB
__device__ __half g_p_i[(size_t)NBH*SSEQ*SSEQ];  // ~50 MB

// ============================================================================
// Complex projection GEMM: C = (Xr + iXi) @ (Wr + iWi)
// X: [2048, 768] fp32 row-major, W: [768, 768] fp32 row-major, C: fp32.
// Block = 64x64 tile, 128 threads (4 warps, 2x2 of 32x32), K-chunks of 16.
// ============================================================================
__global__ void proj_gemm_kernel(const float* __restrict__ Xr, const float* __restrict__ Xi,
                                 const float* __restrict__ Wr, const float* __restrict__ Wi,
                                 int out_sel)
{
    float *Cr, *Ci;
    if (out_sel == 0)      { Cr = g_q_r; Ci = g_q_i; }
    else if (out_sel == 1) { Cr = g_k_r; Ci = g_k_i; }
    else                   { Cr = g_v_r; Ci = g_v_i; }

    const int N = DKK, K = DD;
    const int n0 = blockIdx.x * 64;
    const int m0 = blockIdx.y * 64;

    __shared__ __half sAr[64*24], sAi[64*24];   // [m][k], ld 24
    __shared__ __half sBr[16*72], sBi[16*72];   // [k][n], ld 72

    const int tid  = threadIdx.x;
    const int warp = tid >> 5;
    const int wm   = warp >> 1;
    const int wn   = warp & 1;

    wmma::fragment<wmma::accumulator,16,16,16,float> accR[2][2], accI[2][2];
    #pragma unroll
    for (int i = 0; i < 2; i++)
        #pragma unroll
        for (int j = 0; j < 2; j++) {
            wmma::fill_fragment(accR[i][j], 0.0f);
            wmma::fill_fragment(accI[i][j], 0.0f);
        }

    for (int k0 = 0; k0 < K; k0 += 16) {
        #pragma unroll
        for (int e = 0; e < 8; e++) {           // A: 64x16
            int idx = e*128 + tid;
            int m = idx >> 4, kk = idx & 15;
            sAr[m*24+kk] = __float2half(Xr[(size_t)(m0+m)*K + k0+kk]);
            sAi[m*24+kk] = __float2half(Xi[(size_t)(m0+m)*K + k0+kk]);
        }
        #pragma unroll
        for (int e = 0; e < 8; e++) {           // B: 16x64
            int idx = e*128 + tid;
            int kk = idx >> 6, n = idx & 63;
            sBr[kk*72+n] = __float2half(Wr[(size_t)(k0+kk)*N + n0+n]);
            sBi[kk*72+n] = __float2half(Wi[(size_t)(k0+kk)*N + n0+n]);
        }
        __syncthreads();

        wmma::fragment<wmma::matrix_a,16,16,16,__half,wmma::row_major> aR[2], aI[2], aNI[2];
        wmma::fragment<wmma::matrix_b,16,16,16,__half,wmma::row_major> bR[2], bI[2];
        #pragma unroll
        for (int i = 0; i < 2; i++) {
            wmma::load_matrix_sync(aR[i], &sAr[(wm*32+i*16)*24], 24);
            wmma::load_matrix_sync(aI[i], &sAi[(wm*32+i*16)*24], 24);
            #pragma unroll
            for (int x = 0; x < aI[i].num_elements; x++) aNI[i].x[x] = __hneg(aI[i].x[x]);
        }
        #pragma unroll
        for (int j = 0; j < 2; j++) {
            wmma::load_matrix_sync(bR[j], &sBr[wn*32+j*16], 72);
            wmma::load_matrix_sync(bI[j], &sBi[wn*32+j*16], 72);
        }
        #pragma unroll
        for (int i = 0; i < 2; i++)
            #pragma unroll
            for (int j = 0; j < 2; j++) {
                wmma::mma_sync(accR[i][j], aR[i],  bR[j], accR[i][j]); // +Xr*Wr
                wmma::mma_sync(accR[i][j], aNI[i], bI[j], accR[i][j]); // -Xi*Wi
                wmma::mma_sync(accI[i][j], aR[i],  bI[j], accI[i][j]); // +Xr*Wi
                wmma::mma_sync(accI[i][j], aI[i],  bR[j], accI[i][j]); // +Xi*Wr
            }
        __syncthreads();
    }

    #pragma unroll
    for (int i = 0; i < 2; i++)
        #pragma unroll
        for (int j = 0; j < 2; j++) {
            int m = m0 + wm*32 + i*16;
            int n = n0 + wn*32 + j*16;
            wmma::store_matrix_sync(&Cr[(size_t)m*N + n], accR[i][j], N, wmma::mem_row_major);
            wmma::store_matrix_sync(&Ci[(size_t)m*N + n], accI[i][j], N, wmma::mem_row_major);
        }
}

// ============================================================================
// v += bias (broadcast over rows)
// ============================================================================
__global__ void bias_v_kernel(const float* __restrict__ bvr, const float* __restrict__ bvi)
{
    int idx = blockIdx.x * 256 + threadIdx.x;
    if (idx < MROWS*DVV) {
        int n = idx % DVV;
        g_v_r[idx] += bvr[n];
        g_v_i[idx] += bvi[n];
    }
}

// ============================================================================
// cb = (hidden_r + i hidden_i) @ (Wcb_r + i Wcb_i), stored transposed as [b,h,t]
// One warp per (row, head).
// ============================================================================
__global__ void cb_kernel(const float* __restrict__ Xr, const float* __restrict__ Xi,
                          const float* __restrict__ Wr, const float* __restrict__ Wi)
{
    int gw = (blockIdx.x * blockDim.x + threadIdx.x) >> 5;
    int lane = threadIdx.x & 31;
    if (gw >= MROWS*HH) return;
    int row = gw / HH;
    int h   = gw % HH;
    int b   = row / SSEQ;
    int t   = row % SSEQ;

    float sr = 0.f, si = 0.f;
    for (int k = lane; k < DD; k += 32) {
        float xr = Xr[(size_t)row*DD + k];
        float xi = Xi[(size_t)row*DD + k];
        float wr = Wr[k*HH + h];
        float wi = Wi[k*HH + h];
        sr += xr*wr - xi*wi;
        si += xr*wi + xi*wr;
    }
    #pragma unroll
    for (int o = 16; o; o >>= 1) {
        sr += __shfl_down_sync(0xffffffffu, sr, o);
        si += __shfl_down_sync(0xffffffffu, si, o);
    }
    if (lane == 0) {
        g_cb_r[(b*HH + h)*SSEQ + t] = sr;
        g_cb_i[(b*HH + h)*SSEQ + t] = si;
    }
}

// ============================================================================
// Scores: s[b,h,s,t] = sum_d q[b,s,d] * (m[h,d] * k[b,t,d])   (complex)
// mix-scaling fused into B-tile staging. Raw scores to g_s_{r,i} (fp32).
// ============================================================================
__global__ void score_kernel(const float* __restrict__ mix_r, const float* __restrict__ mix_i)
{
    const int t0 = blockIdx.x * 64;
    const int s0 = blockIdx.y * 64;
    const int bh = blockIdx.z;
    const int b  = bh / HH;
    const int h  = bh % HH;

    __shared__ __half sQr[64*24], sQi[64*24];   // [s][k], ld 24 (row-major A)
    __shared__ __half sWr[64*24], sWi[64*24];   // [t][k], ld 24 (col-major B)

    const float* qr = g_q_r + (size_t)(b*SSEQ + s0)*DKK;
    const float* qi = g_q_i + (size_t)(b*SSEQ + s0)*DKK;
    const float* kr = g_k_r + (size_t)(b*SSEQ + t0)*DKK;
    const float* ki = g_k_i + (size_t)(b*SSEQ + t0)*DKK;
    const float* mr = mix_r + h*DKK;
    const float* mi = mix_i + h*DKK;

    const int tid  = threadIdx.x;
    const int warp = tid >> 5;
    const int wm   = warp >> 1;
    const int wn   = warp & 1;

    wmma::fragment<wmma::accumulator,16,16,16,float> accR[2][2], accI[2][2];
    #pragma unroll
    for (int i = 0; i < 2; i++)
        #pragma unroll
        for (int j = 0; j < 2; j++) {
            wmma::fill_fragment(accR[i][j], 0.0f);
            wmma::fill_fragment(accI[i][j], 0.0f);
        }

    for (int k0 = 0; k0 < DKK; k0 += 16) {
        #pragma unroll
        for (int e = 0; e < 8; e++) {           // Q: 64x16
            int idx = e*128 + tid;
            int m = idx >> 4, kk = idx & 15;
            sQr[m*24+kk] = __float2half(qr[(size_t)m*DKK + k0+kk]);
            sQi[m*24+kk] = __float2half(qi[(size_t)m*DKK + k0+kk]);
        }
        #pragma unroll
        for (int e = 0; e < 8; e++) {           // W = m*k: 64 t x 16 k
            int idx = e*128 + tid;
            int tt = idx >> 4, kk = idx & 15;
            float akr = kr[(size_t)tt*DKK + k0+kk];
            float aki = ki[(size_t)tt*DKK + k0+kk];
            float amr = mr[k0+kk];
            float ami = mi[k0+kk];
            sWr[tt*24+kk] = __float2half(amr*akr - ami*aki);
            sWi[tt*24+kk] = __float2half(amr*aki + ami*akr);
        }
        __syncthreads();

        wmma::fragment<wmma::matrix_a,16,16,16,__half,wmma::row_major> aR[2], aI[2], aNI[2];
        wmma::fragment<wmma::matrix_b,16,16,16,__half,wmma::col_major> bR[2], bI[2];
        #pragma unroll
        for (int i = 0; i < 2; i++) {
            wmma::load_matrix_sync(aR[i], &sQr[(wm*32+i*16)*24], 24);
            wmma::load_matrix_sync(aI[i], &sQi[(wm*32+i*16)*24], 24);
            #pragma unroll
            for (int x = 0; x < aI[i].num_elements; x++) aNI[i].x[x] = __hneg(aI[i].x[x]);
        }
        #pragma unroll
        for (int j = 0; j < 2; j++) {
            wmma::load_matrix_sync(bR[j], &sWr[(wn*32+j*16)*24], 24);
            wmma::load_matrix_sync(bI[j], &sWi[(wn*32+j*16)*24], 24);
        }
        #pragma unroll
        for (int i = 0; i < 2; i++)
            #pragma unroll
            for (int j = 0; j < 2; j++) {
                wmma::mma_sync(accR[i][j], aR[i],  bR[j], accR[i][j]); // +qr*wr
                wmma::mma_sync(accR[i][j], aNI[i], bI[j], accR[i][j]); // -qi*wi
                wmma::mma_sync(accI[i][j], aR[i],  bI[j], accI[i][j]); // +qr*wi
                wmma::mma_sync(accI[i][j], aI[i],  bR[j], accI[i][j]); // +qi*wr
            }
        __syncthreads();
    }

    #pragma unroll
    for (int i = 0; i < 2; i++)
        #pragma unroll
        for (int j = 0; j < 2; j++) {
            int s = s0 + wm*32 + i*16;
            int t = t0 + wn*32 + j*16;
            size_t off = ((size_t)bh*SSEQ + s)*SSEQ + t;
            wmma::store_matrix_sync(&g_s_r[off], accR[i][j], SSEQ, wmma::mem_row_major);
            wmma::store_matrix_sync(&g_s_i[off], accI[i][j], SSEQ, wmma::mem_row_major);
        }
}

// ============================================================================
// Softmax over t (per b,h,s, separately for real/imag score): p = softmax((s+cb)/8)
// One block (256 thr) per row of 1024; 4 elements per thread.
// ============================================================================
__global__ void softmax_kernel()
{
    const int srow = blockIdx.x;     // query index s
    const int bh   = blockIdx.y;
    const int comp = blockIdx.z;     // 0 = real, 1 = imag

    const float*  Sm = comp ? g_s_i  : g_s_r;
    const float*  Cb = comp ? g_cb_i : g_cb_r;
    __half*       P  = comp ? g_p_i  : g_p_r;

    const size_t rowoff = ((size_t)bh*SSEQ + srow)*SSEQ;
    const float* row = Sm + rowoff;
    const float* cb  = Cb + (size_t)bh*SSEQ;

    __shared__ float red[8];
    __shared__ float bcast;

    const int tid  = threadIdx.x;
    const int lane = tid & 31;
    const int w    = tid >> 5;

    float x[4];
    float mx = -1e30f;
    #pragma unroll
    for (int j = 0; j < 4; j++) {
        int t = tid + j*256;
        x[j] = (row[t] + cb[t]) * 0.125f;
        mx = fmaxf(mx, x[j]);
    }
    #pragma unroll
    for (int o = 16; o; o >>= 1) mx = fmaxf(mx, __shfl_xor_sync(0xffffffffu, mx, o));
    if (lane == 0) red[w] = mx;
    __syncthreads();
    if (tid == 0) {
        float mm = red[0];
        #pragma unroll
        for (int i = 1; i < 8; i++) mm = fmaxf(mm, red[i]);
        bcast = mm;
    }
    __syncthreads();
    mx = bcast;

    float sum = 0.f;
    #pragma unroll
    for (int j = 0; j < 4; j++) {
        x[j] = __expf(x[j] - mx);
        sum += x[j];
    }
    #pragma unroll
    for (int o = 16; o; o >>= 1) sum += __shfl_xor_sync(0xffffffffu, sum, o);
    __syncthreads();            // protect red[] reuse
    if (lane == 0) red[w] = sum;
    __syncthreads();
    if (tid == 0) {
        float ss = 0.f;
        #pragma unroll
        for (int i = 0; i < 8; i++) ss += red[i];
        bcast = ss;
    }
    __syncthreads();
    float inv = 1.0f / bcast;

    #pragma unroll
    for (int j = 0; j < 4; j++) {
        int t = tid + j*256;
        P[rowoff + t] = __float2half(x[j] * inv);
    }
}

// ============================================================================
// Output: c[b,h,s,:] = (pr + i pi) @ (vr + i vi)_head, written to [2,B,S,DV].
// Block = 64 (s) x 64 (head dv), 128 threads, K = 1024 over t.
// A (p) loaded directly from global halves; B (v) staged fp32->half in smem.
// ============================================================================
__global__ void pv_kernel(float* __restrict__ out)
{
    const int s0 = blockIdx.x * 64;
    const int bh = blockIdx.y;
    const int b  = bh / HH;
    const int h  = bh % HH;

    __shared__ __half sVr[16*72], sVi[16*72];   // [t][n], ld 72

    const __half* pr = g_p_r + (size_t)bh*SSEQ*SSEQ;
    const __half* pi = g_p_i + (size_t)bh*SSEQ*SSEQ;
    const float*  vr = g_v_r + (size_t)(b*SSEQ)*DVV + h*DHH;
    const float*  vi = g_v_i + (size_t)(b*SSEQ)*DVV + h*DHH;

    const int tid  = threadIdx.x;
    const int warp = tid >> 5;
    const int wm   = warp >> 1;
    const int wn   = warp & 1;

    wmma::fragment<wmma::accumulator,16,16,16,float> accR[2][2], accI[2][2];
    #pragma unroll
    for (int i = 0; i < 2; i++)
        #pragma unroll
        for (int j = 0; j < 2; j++) {
            wmma::fill_fragment(accR[i][j], 0.0f);
            wmma::fill_fragment(accI[i][j], 0.0f);
        }

    for (int k0 = 0; k0 < SSEQ; k0 += 16) {
        #pragma unroll
        for (int e = 0; e < 8; e++) {           // V: 16 t x 64 n
            int idx = e*128 + tid;
            int kk = idx >> 6, n = idx & 63;
            sVr[kk*72+n] = __float2half(vr[(size_t)(k0+kk)*DVV + n]);
            sVi[kk*72+n] = __float2half(vi[(size_t)(k0+kk)*DVV + n]);
        }
        __syncthreads();

        wmma::fragment<wmma::matrix_a,16,16,16,__half,wmma::row_major> pR[2], pI[2], pNI[2];
        wmma::fragment<wmma::matrix_b,16,16,16,__half,wmma::row_major> bR[2], bI[2];
        #pragma unroll
        for (int i = 0; i < 2; i++) {
            const size_t arow = (size_t)(s0 + wm*32 + i*16)*SSEQ + k0;
            wmma::load_matrix_sync(pR[i], pr + arow, SSEQ);
            wmma::load_matrix_sync(pI[i], pi + arow, SSEQ);
            #pragma unroll
            for (int x = 0; x < pI[i].num_elements; x++) pNI[i].x[x] = __hneg(pI[i].x[x]);
        }
        #pragma unroll
        for (int j = 0; j < 2; j++) {
            wmma::load_matrix_sync(bR[j], &sVr[wn*32+j*16], 72);
            wmma::load_matrix_sync(bI[j], &sVi[wn*32+j*16], 72);
        }
        #pragma unroll
        for (int i = 0; i < 2; i++)
            #pragma unroll
            for (int j = 0; j < 2; j++) {
                wmma::mma_sync(accR[i][j], pR[i],  bR[j], accR[i][j]); // +pr*vr
                wmma::mma_sync(accR[i][j], pNI[i], bI[j], accR[i][j]); // -pi*vi
                wmma::mma_sync(accI[i][j], pR[i],  bI[j], accI[i][j]); // +pr*vi
                wmma::mma_sync(accI[i][j], pI[i],  bR[j], accI[i][j]); // +pi*vr
            }
        __syncthreads();
    }

    #pragma unroll
    for (int i = 0; i < 2; i++)
        #pragma unroll
        for (int j = 0; j < 2; j++) {
            int s = s0 + wm*32 + i*16;
            int n = h*DHH + wn*32 + j*16;
            size_t off_r = ((size_t)b*SSEQ + s)*DVV + n;
            size_t off_i = (size_t)BB*SSEQ*DVV + off_r;
            wmma::store_matrix_sync(out + off_r, accR[i][j], DVV, wmma::mem_row_major);
            wmma::store_matrix_sync(out + off_i, accI[i][j], DVV, wmma::mem_row_major);
        }
}

// ============================================================================
// Launcher
// ============================================================================
extern "C" void kernel_launch(void* const* d_in, const int* in_sizes, int n_in,
                              void* d_out, int out_size)
{
    const float* hr   = (const float*)d_in[0];
    const float* hi   = (const float*)d_in[1];
    const float* Wqr  = (const float*)d_in[2];
    const float* Wqi  = (const float*)d_in[3];
    const float* Wkr  = (const float*)d_in[4];
    const float* Wki  = (const float*)d_in[5];
    const float* Wcbr = (const float*)d_in[6];
    const float* Wcbi = (const float*)d_in[7];
    const float* Wvr  = (const float*)d_in[8];
    const float* Wvi  = (const float*)d_in[9];
    const float* bvr  = (const float*)d_in[10];
    const float* bvi  = (const float*)d_in[11];
    const float* mixr = (const float*)d_in[12];
    const float* mixi = (const float*)d_in[13];
    float* out = (float*)d_out;

    dim3 gProj(DKK/64, MROWS/64);   // (12, 32)
    proj_gemm_kernel<<<gProj, 128>>>(hr, hi, Wqr, Wqi, 0);
    proj_gemm_kernel<<<gProj, 128>>>(hr, hi, Wkr, Wki, 1);
    proj_gemm_kernel<<<gProj, 128>>>(hr, hi, Wvr, Wvi, 2);

    bias_v_kernel<<<(MROWS*DVV + 255)/256, 256>>>(bvr, bvi);
    cb_kernel<<<(MROWS*HH*32 + 255)/256, 256>>>(hr, hi, Wcbr, Wcbi);

    score_kernel<<<dim3(SSEQ/64, SSEQ/64, NBH), 128>>>(mixr, mixi);   // (16,16,24)
    softmax_kernel<<<dim3(SSEQ, NBH, 2), 256>>>();
    pv_kernel<<<dim3(SSEQ/64, NBH), 128>>>(out);                      // (16,24)
}

// round 2
// speedup vs baseline: 1.5395x; 1.5395x over previous
#include <cuda_runtime.h>
#include <cuda_fp16.h>
#include <mma.h>
#include <cstdint>

using namespace nvcuda;

// Problem constants
#define BB   2
#define SSEQ 1024
#define DD   768
#define HH   12
#define DKK  768
#define DVV  768
#define DHH  64
#define MROWS (BB*SSEQ)  // 2048
#define NBH   (BB*HH)    // 24

#define KC   32          // K-chunk
#define LDA  40          // padded ld for [row][k] tiles (conflict-free ldmatrix)
#define LDB  72          // padded ld for [k][n] tiles

// ---------------- scratch (device globals) ----------------
__device__ float  g_q_r[MROWS*DKK];
__device__ float  g_q_i[MROWS*DKK];
__device__ float  g_k_r[MROWS*DKK];
__device__ float  g_k_i[MROWS*DKK];
__device__ float  g_v_r[MROWS*DVV];
__device__ float  g_v_i[MROWS*DVV];
__device__ float  g_cb_r[NBH*SSEQ];
__device__ float  g_cb_i[NBH*SSEQ];
__device__ float  g_s_r[(size_t)NBH*SSEQ*SSEQ];
__device__ float  g_s_i[(size_t)NBH*SSEQ*SSEQ];
__device__ __half g_p_r[(size_t)NBH*SSEQ*SSEQ];
__device__ __half g_p_i[(size_t)NBH*SSEQ*SSEQ];
// half-precision staging arrays
__device__ __half g_hh_r[MROWS*DD],  g_hh_i[MROWS*DD];
__device__ __half g_wqh_r[DD*DKK],   g_wqh_i[DD*DKK];
__device__ __half g_wkh_r[DD*DKK],   g_wkh_i[DD*DKK];
__device__ __half g_wvh_r[DD*DVV],   g_wvh_i[DD*DVV];
__device__ __half g_qh_r[MROWS*DKK], g_qh_i[MROWS*DKK];
__device__ __half g_mkh_r[(size_t)NBH*SSEQ*DKK];
__device__ __half g_mkh_i[(size_t)NBH*SSEQ*DKK];

// ---------------- cp.async helpers ----------------
__device__ __forceinline__ void cp16(void* smem_dst, const void* gmem_src) {
    uint32_t s = (uint32_t)__cvta_generic_to_shared(smem_dst);
    asm volatile("cp.async.cg.shared.global [%0], [%1], 16;\n" :: "r"(s), "l"(gmem_src));
}
__device__ __forceinline__ void cp_commit() { asm volatile("cp.async.commit_group;\n"); }
template<int N>
__device__ __forceinline__ void cp_wait() { asm volatile("cp.async.wait_group %0;\n" :: "n"(N)); }

// ============================================================================
// float -> half conversion (vectorized x4)
// ============================================================================
__global__ void f2h_kernel(const float* __restrict__ src, __half* __restrict__ dst, int n)
{
    int i = (blockIdx.x*256 + threadIdx.x) * 4;
    if (i < n) {
        float4 v = *reinterpret_cast<const float4*>(src + i);
        *reinterpret_cast<__half2*>(dst + i)     = __floats2half2_rn(v.x, v.y);
        *reinterpret_cast<__half2*>(dst + i + 2) = __floats2half2_rn(v.z, v.w);
    }
}

// ============================================================================
// mk[bh, t, d] = mix[h, d] * k[b, t, d]  (complex, fp32 -> half), vectorized x4
// ============================================================================
__global__ void prep_mk_kernel(const float* __restrict__ mix_r, const float* __restrict__ mix_i)
{
    size_t idx = ((size_t)blockIdx.x*256 + threadIdx.x) * 4;
    const size_t total = (size_t)NBH*SSEQ*DKK;
    if (idx >= total) return;
    int d = (int)(idx % DKK);
    size_t rest = idx / DKK;
    int t  = (int)(rest % SSEQ);
    int bh = (int)(rest / SSEQ);
    int b = bh / HH, h = bh % HH;

    size_t koff = ((size_t)(b*SSEQ + t))*DKK + d;
    float4 kr = *reinterpret_cast<const float4*>(&g_k_r[koff]);
    float4 ki = *reinterpret_cast<const float4*>(&g_k_i[koff]);
    float4 mr = *reinterpret_cast<const float4*>(&mix_r[h*DKK + d]);
    float4 mi = *reinterpret_cast<const float4*>(&mix_i[h*DKK + d]);

    float rr[4], ii[4];
    rr[0] = mr.x*kr.x - mi.x*ki.x;  ii[0] = mr.x*ki.x + mi.x*kr.x;
    rr[1] = mr.y*kr.y - mi.y*ki.y;  ii[1] = mr.y*ki.y + mi.y*kr.y;
    rr[2] = mr.z*kr.z - mi.z*ki.z;  ii[2] = mr.z*ki.z + mi.z*kr.z;
    rr[3] = mr.w*kr.w - mi.w*ki.w;  ii[3] = mr.w*ki.w + mi.w*kr.w;

    *reinterpret_cast<__half2*>(&g_mkh_r[idx])   = __floats2half2_rn(rr[0], rr[1]);
    *reinterpret_cast<__half2*>(&g_mkh_r[idx+2]) = __floats2half2_rn(rr[2], rr[3]);
    *reinterpret_cast<__half2*>(&g_mkh_i[idx])   = __floats2half2_rn(ii[0], ii[1]);
    *reinterpret_cast<__half2*>(&g_mkh_i[idx+2]) = __floats2half2_rn(ii[2], ii[3]);
}

// ============================================================================
// Complex projection GEMM (half in, fp32 out): C = (Xr+iXi)(Wr+iWi)
// 128x64 tile, 256 threads (8 warps, 4x2), KC=32, cp.async double buffer.
// A = g_hh (row-major M x K), W row-major K x N.
// ============================================================================
__global__ void proj_gemm2(const __half* __restrict__ Wr, const __half* __restrict__ Wi,
                           int out_sel)
{
    float *Cr, *Ci;
    if (out_sel == 0)      { Cr = g_q_r; Ci = g_q_i; }
    else if (out_sel == 1) { Cr = g_k_r; Ci = g_k_i; }
    else                   { Cr = g_v_r; Ci = g_v_i; }

    const int n0 = blockIdx.x * 64;
    const int m0 = blockIdx.y * 128;

    extern __shared__ __half smem[];
    __half* sA = smem;                     // [stage][type][128*LDA]
    __half* sB = smem + 2*2*128*LDA;       // [stage][type][KC*LDB]

    const int tid  = threadIdx.x;
    const int warp = tid >> 5;
    const int wm   = warp >> 1;   // 0..3
    const int wn   = warp & 1;    // 0..1

    const __half* A0 = g_hh_r;
    const __half* A1 = g_hh_i;

    auto load_stage = [&](int k0, int stg) {
        __half* sAs = sA + stg*(2*128*LDA);
        __half* sBs = sB + stg*(2*KC*LDB);
        #pragma unroll
        for (int e = 0; e < 4; e++) {                  // A: 2 types * 128 rows * 4 chunks
            int c = e*256 + tid;
            int type = c >> 9;
            int r  = (c >> 2) & 127;
            int cc = c & 3;
            const __half* src = (type ? A1 : A0) + (size_t)(m0 + r)*DD + k0 + cc*8;
            cp16(sAs + type*(128*LDA) + r*LDA + cc*8, src);
        }
        #pragma unroll
        for (int e = 0; e < 2; e++) {                  // B: 2 types * 32 rows * 8 chunks
            int c = e*256 + tid;
            int type = c >> 8;
            int c2 = c & 255;
            int r  = c2 >> 3;
            int cc = c2 & 7;
            const __half* src = (type ? Wi : Wr) + (size_t)(k0 + r)*DKK + n0 + cc*8;
            cp16(sBs + type*(KC*LDB) + r*LDB + cc*8, src);
        }
        cp_commit();
    };

    wmma::fragment<wmma::accumulator,16,16,16,float> accR[2][2], accI[2][2];
    #pragma unroll
    for (int i = 0; i < 2; i++)
        #pragma unroll
        for (int j = 0; j < 2; j++) { wmma::fill_fragment(accR[i][j], 0.f); wmma::fill_fragment(accI[i][j], 0.f); }

    const int NSTEP = DD / KC;   // 24
    load_stage(0, 0);

    for (int ks = 0; ks < NSTEP; ks++) {
        int cur = ks & 1;
        if (ks + 1 < NSTEP) { load_stage((ks+1)*KC, cur^1); cp_wait<1>(); }
        else                { cp_wait<0>(); }
        __syncthreads();

        __half* sAs = sA + cur*(2*128*LDA);
        __half* sBs = sB + cur*(2*KC*LDB);

        #pragma unroll
        for (int kk = 0; kk < KC; kk += 16) {
            wmma::fragment<wmma::matrix_a,16,16,16,__half,wmma::row_major> aR[2], aI[2], aNI[2];
            wmma::fragment<wmma::matrix_b,16,16,16,__half,wmma::row_major> bR[2], bI[2];
            #pragma unroll
            for (int i = 0; i < 2; i++) {
                int row = wm*32 + i*16;
                wmma::load_matrix_sync(aR[i], sAs + row*LDA + kk, LDA);
                wmma::load_matrix_sync(aI[i], sAs + 128*LDA + row*LDA + kk, LDA);
                #pragma unroll
                for (int x = 0; x < aI[i].num_elements; x++) aNI[i].x[x] = __hneg(aI[i].x[x]);
            }
            #pragma unroll
            for (int j = 0; j < 2; j++) {
                int col = wn*32 + j*16;
                wmma::load_matrix_sync(bR[j], sBs + kk*LDB + col, LDB);
                wmma::load_matrix_sync(bI[j], sBs + KC*LDB + kk*LDB + col, LDB);
            }
            #pragma unroll
            for (int i = 0; i < 2; i++)
                #pragma unroll
                for (int j = 0; j < 2; j++) {
                    wmma::mma_sync(accR[i][j], aR[i],  bR[j], accR[i][j]);
                    wmma::mma_sync(accR[i][j], aNI[i], bI[j], accR[i][j]);
                    wmma::mma_sync(accI[i][j], aR[i],  bI[j], accI[i][j]);
                    wmma::mma_sync(accI[i][j], aI[i],  bR[j], accI[i][j]);
                }
        }
        __syncthreads();
    }

    #pragma unroll
    for (int i = 0; i < 2; i++)
        #pragma unroll
        for (int j = 0; j < 2; j++) {
            int m = m0 + wm*32 + i*16;
            int n = n0 + wn*32 + j*16;
            wmma::store_matrix_sync(&Cr[(size_t)m*DKK + n], accR[i][j], DKK, wmma::mem_row_major);
            wmma::store_matrix_sync(&Ci[(size_t)m*DKK + n], accI[i][j], DKK, wmma::mem_row_major);
        }
}

// ============================================================================
// v += bias
// ============================================================================
__global__ void bias_v_kernel(const float* __restrict__ bvr, const float* __restrict__ bvi)
{
    int idx = blockIdx.x * 256 + threadIdx.x;
    if (idx < MROWS*DVV) {
        int n = idx % DVV;
        g_v_r[idx] += bvr[n];
        g_v_i[idx] += bvi[n];
    }
}

// ============================================================================
// cb projection (tiny N=12): one warp per (row, head)
// ============================================================================
__global__ void cb_kernel(const float* __restrict__ Xr, const float* __restrict__ Xi,
                          const float* __restrict__ Wr, const float* __restrict__ Wi)
{
    int gw = (blockIdx.x * blockDim.x + threadIdx.x) >> 5;
    int lane = threadIdx.x & 31;
    if (gw >= MROWS*HH) return;
    int row = gw / HH;
    int h   = gw % HH;
    int b   = row / SSEQ;
    int t   = row % SSEQ;

    float sr = 0.f, si = 0.f;
    for (int k = lane; k < DD; k += 32) {
        float xr = Xr[(size_t)row*DD + k];
        float xi = Xi[(size_t)row*DD + k];
        float wr = Wr[k*HH + h];
        float wi = Wi[k*HH + h];
        sr += xr*wr - xi*wi;
        si += xr*wi + xi*wr;
    }
    #pragma unroll
    for (int o = 16; o; o >>= 1) {
        sr += __shfl_down_sync(0xffffffffu, sr, o);
        si += __shfl_down_sync(0xffffffffu, si, o);
    }
    if (lane == 0) {
        g_cb_r[(b*HH + h)*SSEQ + t] = sr;
        g_cb_i[(b*HH + h)*SSEQ + t] = si;
    }
}

// ============================================================================
// Scores: s[bh, s, t] = sum_d qh[b,s,d] * mkh[bh,t,d]  (complex)
// 128(s) x 64(t) tile, 256 threads, KC=32, cp.async double buffer.
// A = qh row-major [s][d]; B = mkh [t][d] used as col-major k x n.
// ============================================================================
__global__ void score_kernel2()
{
    const int t0 = blockIdx.x * 64;
    const int s0 = blockIdx.y * 128;
    const int bh = blockIdx.z;
    const int b  = bh / HH;

    extern __shared__ __half smem[];
    __half* sA = smem;                     // [stage][type][128*LDA]
    __half* sB = smem + 2*2*128*LDA;       // [stage][type][64*LDA]

    const int tid  = threadIdx.x;
    const int warp = tid >> 5;
    const int wm   = warp >> 1;
    const int wn   = warp & 1;

    const __half* Ar = g_qh_r + (size_t)(b*SSEQ + s0)*DKK;
    const __half* Ai = g_qh_i + (size_t)(b*SSEQ + s0)*DKK;
    const __half* Br = g_mkh_r + ((size_t)bh*SSEQ + t0)*DKK;
    const __half* Bi = g_mkh_i + ((size_t)bh*SSEQ + t0)*DKK;

    auto load_stage = [&](int k0, int stg) {
        __half* sAs = sA + stg*(2*128*LDA);
        __half* sBs = sB + stg*(2*64*LDA);
        #pragma unroll
        for (int e = 0; e < 4; e++) {                  // A: 2 types * 128 rows * 4 chunks
            int c = e*256 + tid;
            int type = c >> 9;
            int r  = (c >> 2) & 127;
            int cc = c & 3;
            const __half* src = (type ? Ai : Ar) + (size_t)r*DKK + k0 + cc*8;
            cp16(sAs + type*(128*LDA) + r*LDA + cc*8, src);
        }
        #pragma unroll
        for (int e = 0; e < 2; e++) {                  // B: 2 types * 64 rows * 4 chunks
            int c = e*256 + tid;
            int type = c >> 8;
            int c2 = c & 255;
            int r  = c2 >> 2;
            int cc = c2 & 3;
            const __half* src = (type ? Bi : Br) + (size_t)r*DKK + k0 + cc*8;
            cp16(sBs + type*(64*LDA) + r*LDA + cc*8, src);
        }
        cp_commit();
    };

    wmma::fragment<wmma::accumulator,16,16,16,float> accR[2][2], accI[2][2];
    #pragma unroll
    for (int i = 0; i < 2; i++)
        #pragma unroll
        for (int j = 0; j < 2; j++) { wmma::fill_fragment(accR[i][j], 0.f); wmma::fill_fragment(accI[i][j], 0.f); }

    const int NSTEP = DKK / KC;   // 24
    load_stage(0, 0);

    for (int ks = 0; ks < NSTEP; ks++) {
        int cur = ks & 1;
        if (ks + 1 < NSTEP) { load_stage((ks+1)*KC, cur^1); cp_wait<1>(); }
        else                { cp_wait<0>(); }
        __syncthreads();

        __half* sAs = sA + cur*(2*128*LDA);
        __half* sBs = sB + cur*(2*64*LDA);

        #pragma unroll
        for (int kk = 0; kk < KC; kk += 16) {
            wmma::fragment<wmma::matrix_a,16,16,16,__half,wmma::row_major> aR[2], aI[2], aNI[2];
            wmma::fragment<wmma::matrix_b,16,16,16,__half,wmma::col_major> bR[2], bI[2];
            #pragma unroll
            for (int i = 0; i < 2; i++) {
                int row = wm*32 + i*16;
                wmma::load_matrix_sync(aR[i], sAs + row*LDA + kk, LDA);
                wmma::load_matrix_sync(aI[i], sAs + 128*LDA + row*LDA + kk, LDA);
                #pragma unroll
                for (int x = 0; x < aI[i].num_elements; x++) aNI[i].x[x] = __hneg(aI[i].x[x]);
            }
            #pragma unroll
            for (int j = 0; j < 2; j++) {
                int col = wn*32 + j*16;
                wmma::load_matrix_sync(bR[j], sBs + col*LDA + kk, LDA);
                wmma::load_matrix_sync(bI[j], sBs + 64*LDA + col*LDA + kk, LDA);
            }
            #pragma unroll
            for (int i = 0; i < 2; i++)
                #pragma unroll
                for (int j = 0; j < 2; j++) {
                    wmma::mma_sync(accR[i][j], aR[i],  bR[j], accR[i][j]); // +qr*wr
                    wmma::mma_sync(accR[i][j], aNI[i], bI[j], accR[i][j]); // -qi*wi
                    wmma::mma_sync(accI[i][j], aR[i],  bI[j], accI[i][j]); // +qr*wi
                    wmma::mma_sync(accI[i][j], aI[i],  bR[j], accI[i][j]); // +qi*wr
                }
        }
        __syncthreads();
    }

    #pragma unroll
    for (int i = 0; i < 2; i++)
        #pragma unroll
        for (int j = 0; j < 2; j++) {
            int s = s0 + wm*32 + i*16;
            int t = t0 + wn*32 + j*16;
            size_t off = ((size_t)bh*SSEQ + s)*SSEQ + t;
            wmma::store_matrix_sync(&g_s_r[off], accR[i][j], SSEQ, wmma::mem_row_major);
            wmma::store_matrix_sync(&g_s_i[off], accI[i][j], SSEQ, wmma::mem_row_major);
        }
}

// ============================================================================
// Softmax over t: p = softmax((s+cb)/8) -> half
// ============================================================================
__global__ void softmax_kernel()
{
    const int srow = blockIdx.x;
    const int bh   = blockIdx.y;
    const int comp = blockIdx.z;

    const float*  Sm = comp ? g_s_i  : g_s_r;
    const float*  Cb = comp ? g_cb_i : g_cb_r;
    __half*       P  = comp ? g_p_i  : g_p_r;

    const size_t rowoff = ((size_t)bh*SSEQ + srow)*SSEQ;
    const float* row = Sm + rowoff;
    const float* cb  = Cb + (size_t)bh*SSEQ;

    __shared__ float red[8];
    __shared__ float bcast;

    const int tid  = threadIdx.x;
    const int lane = tid & 31;
    const int w    = tid >> 5;

    float x[4];
    float mx = -1e30f;
    #pragma unroll
    for (int j = 0; j < 4; j++) {
        int t = tid + j*256;
        x[j] = (row[t] + cb[t]) * 0.125f;
        mx = fmaxf(mx, x[j]);
    }
    #pragma unroll
    for (int o = 16; o; o >>= 1) mx = fmaxf(mx, __shfl_xor_sync(0xffffffffu, mx, o));
    if (lane == 0) red[w] = mx;
    __syncthreads();
    if (tid == 0) {
        float mm = red[0];
        #pragma unroll
        for (int i = 1; i < 8; i++) mm = fmaxf(mm, red[i]);
        bcast = mm;
    }
    __syncthreads();
    mx = bcast;

    float sum = 0.f;
    #pragma unroll
    for (int j = 0; j < 4; j++) {
        x[j] = __expf(x[j] - mx);
        sum += x[j];
    }
    #pragma unroll
    for (int o = 16; o; o >>= 1) sum += __shfl_xor_sync(0xffffffffu, sum, o);
    __syncthreads();
    if (lane == 0) red[w] = sum;
    __syncthreads();
    if (tid == 0) {
        float ss = 0.f;
        #pragma unroll
        for (int i = 0; i < 8; i++) ss += red[i];
        bcast = ss;
    }
    __syncthreads();
    float inv = 1.0f / bcast;

    #pragma unroll
    for (int j = 0; j < 4; j++) {
        int t = tid + j*256;
        P[rowoff + t] = __float2half(x[j] * inv);
    }
}

// ============================================================================
// Output: c = (pr+ipi) @ (vr+ivi)_head -> [2,B,S,DV]
// ============================================================================
__global__ void pv_kernel(float* __restrict__ out)
{
    const int s0 = blockIdx.x * 64;
    const int bh = blockIdx.y;
    const int b  = bh / HH;
    const int h  = bh % HH;

    __shared__ __half sVr[16*72], sVi[16*72];

    const __half* pr = g_p_r + (size_t)bh*SSEQ*SSEQ;
    const __half* pi = g_p_i + (size_t)bh*SSEQ*SSEQ;
    const float*  vr = g_v_r + (size_t)(b*SSEQ)*DVV + h*DHH;
    const float*  vi = g_v_i + (size_t)(b*SSEQ)*DVV + h*DHH;

    const int tid  = threadIdx.x;
    const int warp = tid >> 5;
    const int wm   = warp >> 1;
    const int wn   = warp & 1;

    wmma::fragment<wmma::accumulator,16,16,16,float> accR[2][2], accI[2][2];
    #pragma unroll
    for (int i = 0; i < 2; i++)
        #pragma unroll
        for (int j = 0; j < 2; j++) { wmma::fill_fragment(accR[i][j], 0.f); wmma::fill_fragment(accI[i][j], 0.f); }

    for (int k0 = 0; k0 < SSEQ; k0 += 16) {
        #pragma unroll
        for (int e = 0; e < 8; e++) {
            int idx = e*128 + tid;
            int kk = idx >> 6, n = idx & 63;
            sVr[kk*72+n] = __float2half(vr[(size_t)(k0+kk)*DVV + n]);
            sVi[kk*72+n] = __float2half(vi[(size_t)(k0+kk)*DVV + n]);
        }
        __syncthreads();

        wmma::fragment<wmma::matrix_a,16,16,16,__half,wmma::row_major> pR[2], pI[2], pNI[2];
        wmma::fragment<wmma::matrix_b,16,16,16,__half,wmma::row_major> bR[2], bI[2];
        #pragma unroll
        for (int i = 0; i < 2; i++) {
            const size_t arow = (size_t)(s0 + wm*32 + i*16)*SSEQ + k0;
            wmma::load_matrix_sync(pR[i], pr + arow, SSEQ);
            wmma::load_matrix_sync(pI[i], pi + arow, SSEQ);
            #pragma unroll
            for (int x = 0; x < pI[i].num_elements; x++) pNI[i].x[x] = __hneg(pI[i].x[x]);
        }
        #pragma unroll
        for (int j = 0; j < 2; j++) {
            wmma::load_matrix_sync(bR[j], &sVr[wn*32+j*16], 72);
            wmma::load_matrix_sync(bI[j], &sVi[wn*32+j*16], 72);
        }
        #pragma unroll
        for (int i = 0; i < 2; i++)
            #pragma unroll
            for (int j = 0; j < 2; j++) {
                wmma::mma_sync(accR[i][j], pR[i],  bR[j], accR[i][j]);
                wmma::mma_sync(accR[i][j], pNI[i], bI[j], accR[i][j]);
                wmma::mma_sync(accI[i][j], pR[i],  bI[j], accI[i][j]);
                wmma::mma_sync(accI[i][j], pI[i],  bR[j], accI[i][j]);
            }
        __syncthreads();
    }

    #pragma unroll
    for (int i = 0; i < 2; i++)
        #pragma unroll
        for (int j = 0; j < 2; j++) {
            int s = s0 + wm*32 + i*16;
            int n = h*DHH + wn*32 + j*16;
            size_t off_r = ((size_t)b*SSEQ + s)*DVV + n;
            size_t off_i = (size_t)BB*SSEQ*DVV + off_r;
            wmma::store_matrix_sync(out + off_r, accR[i][j], DVV, wmma::mem_row_major);
            wmma::store_matrix_sync(out + off_i, accI[i][j], DVV, wmma::mem_row_major);
        }
}

// ============================================================================
// Launcher
// ============================================================================
extern "C" void kernel_launch(void* const* d_in, const int* in_sizes, int n_in,
                              void* d_out, int out_size)
{
    const float* hr   = (const float*)d_in[0];
    const float* hi   = (const float*)d_in[1];
    const float* Wqr  = (const float*)d_in[2];
    const float* Wqi  = (const float*)d_in[3];
    const float* Wkr  = (const float*)d_in[4];
    const float* Wki  = (const float*)d_in[5];
    const float* Wcbr = (const float*)d_in[6];
    const float* Wcbi = (const float*)d_in[7];
    const float* Wvr  = (const float*)d_in[8];
    const float* Wvi  = (const float*)d_in[9];
    const float* bvr  = (const float*)d_in[10];
    const float* bvi  = (const float*)d_in[11];
    const float* mixr = (const float*)d_in[12];
    const float* mixi = (const float*)d_in[13];
    float* out = (float*)d_out;

    const int SCORE_SMEM = (2*2*128*LDA + 2*2*64*LDA) * (int)sizeof(__half);   // 61440
    const int PROJ_SMEM  = (2*2*128*LDA + 2*2*KC*LDB) * (int)sizeof(__half);   // 59392
    cudaFuncSetAttribute(score_kernel2, cudaFuncAttributeMaxDynamicSharedMemorySize, SCORE_SMEM);
    cudaFuncSetAttribute(proj_gemm2,    cudaFuncAttributeMaxDynamicSharedMemorySize, PROJ_SMEM);

    // resolve device-global symbol addresses for f2h targets
    __half *hh_r, *hh_i, *wqh_r, *wqh_i, *wkh_r, *wkh_i, *wvh_r, *wvh_i, *qh_r, *qh_i;
    float  *qr32, *qi32;
    cudaGetSymbolAddress((void**)&hh_r,  g_hh_r);
    cudaGetSymbolAddress((void**)&hh_i,  g_hh_i);
    cudaGetSymbolAddress((void**)&wqh_r, g_wqh_r);
    cudaGetSymbolAddress((void**)&wqh_i, g_wqh_i);
    cudaGetSymbolAddress((void**)&wkh_r, g_wkh_r);
    cudaGetSymbolAddress((void**)&wkh_i, g_wkh_i);
    cudaGetSymbolAddress((void**)&wvh_r, g_wvh_r);
    cudaGetSymbolAddress((void**)&wvh_i, g_wvh_i);
    cudaGetSymbolAddress((void**)&qh_r,  g_qh_r);
    cudaGetSymbolAddress((void**)&qh_i,  g_qh_i);
    cudaGetSymbolAddress((void**)&qr32,  g_q_r);
    cudaGetSymbolAddress((void**)&qi32,  g_q_i);

    const int NH = MROWS*DD;    // 1572864
    const int NW = DD*DKK;      // 589824
    f2h_kernel<<<(NH/4 + 255)/256, 256>>>(hr,  hh_r,  NH);
    f2h_kernel<<<(NH/4 + 255)/256, 256>>>(hi,  hh_i,  NH);
    f2h_kernel<<<(NW/4 + 255)/256, 256>>>(Wqr, wqh_r, NW);
    f2h_kernel<<<(NW/4 + 255)/256, 256>>>(Wqi, wqh_i, NW);
    f2h_kernel<<<(NW/4 + 255)/256, 256>>>(Wkr, wkh_r, NW);
    f2h_kernel<<<(NW/4 + 255)/256, 256>>>(Wki, wkh_i, NW);
    f2h_kernel<<<(NW/4 + 255)/256, 256>>>(Wvr, wvh_r, NW);
    f2h_kernel<<<(NW/4 + 255)/256, 256>>>(Wvi, wvh_i, NW);

    dim3 gProj(DKK/64, MROWS/128);   // (12, 16)
    proj_gemm2<<<gProj, 256, PROJ_SMEM>>>(wqh_r, wqh_i, 0);
    proj_gemm2<<<gProj, 256, PROJ_SMEM>>>(wkh_r, wkh_i, 1);
    proj_gemm2<<<gProj, 256, PROJ_SMEM>>>(wvh_r, wvh_i, 2);

    // half copies of q; mk = mix * k (half)
    const int NQ = MROWS*DKK;
    f2h_kernel<<<(NQ/4 + 255)/256, 256>>>(qr32, qh_r, NQ);
    f2h_kernel<<<(NQ/4 + 255)/256, 256>>>(qi32, qh_i, NQ);
    {
        size_t total = (size_t)NBH*SSEQ*DKK;
        int blocks = (int)((total/4 + 255)/256);
        prep_mk_kernel<<<blocks, 256>>>(mixr, mixi);
    }

    bias_v_kernel<<<(MROWS*DVV + 255)/256, 256>>>(bvr, bvi);
    cb_kernel<<<(MROWS*HH*32 + 255)/256, 256>>>(hr, hi, Wcbr, Wcbi);

    score_kernel2<<<dim3(SSEQ/64, SSEQ/128, NBH), 256, SCORE_SMEM>>>();  // (16,8,24)
    softmax_kernel<<<dim3(SSEQ, NBH, 2), 256>>>();
    pv_kernel<<<dim3(SSEQ/64, NBH), 128>>>(out);
}